// round 16
// baseline (speedup 1.0000x reference)
#include <cuda_runtime.h>
#include <cuda_bf16.h>
#include <math.h>

#define BB 4
#define CIN 128
#define TQ 256
#define TS 257
#define TD 65
#define HID 256
#define COUT 512
#define NHEAD 8
#define EDIM 32

typedef unsigned short u16;

// ---------------- scratch (static device globals; no allocation) ----------------
__device__ u16   g_pooledh[BB*CIN*TQ*TD];
__device__ u16   g_pooledl[BB*CIN*TQ*TD];
__device__ u16   g_corrch[BB*CIN*TQ*260];
__device__ u16   g_corrcl[BB*CIN*TQ*260];
__device__ u16   g_wqkvh[768*CIN],  g_wqkvl[768*CIN];
__device__ u16   g_wsch[COUT*CIN],  g_wscl[COUT*CIN];
__device__ u16   g_waggh[COUT*HID], g_waggl[COUT*HID];
__device__ float g_kv[BB*2*HID*TQ*260];
__device__ float g_q[BB*HID*TQ*TD];
__device__ float g_res[BB*COUT*TQ*TD];
__device__ float g_att[BB*HID*TQ*TD];
__device__ float g_agg[BB*COUT*TQ*TD];
__device__ int   g_sidx[BB*260];
__device__ int   g_cnt[BB];
__device__ float g_partial[16*130*2];
__device__ float g_partial1[16*512*2];
__device__ float g_stats[16*2];
__device__ float g_stats_sc[16*2];
__device__ float g_stats1[16*2];
__device__ float g_stats2[16*2];

// ---------------- helpers ----------------
__device__ __forceinline__ float fexp(float x) {
    float y = x * 1.44269504f;
    y = fmaxf(y, -126.0f);
    float z = y + 12582912.0f;
    int   r = __float_as_int(z) - 0x4B400000;
    float f = y - (z - 12582912.0f);
    float p =        1.53832606e-4f;
    p = fmaf(p, f, 1.33978284e-3f);
    p = fmaf(p, f, 9.61833310e-3f);
    p = fmaf(p, f, 5.55036624e-2f);
    p = fmaf(p, f, 2.40226500e-1f);
    p = fmaf(p, f, 6.93147182e-1f);
    p = fmaf(p, f, 1.0f);
    return p * __int_as_float((r + 127) << 23);
}
__device__ __forceinline__ unsigned pk2(float x, float y) {
    __nv_bfloat162 t = __floats2bfloat162_rn(x, y);
    return *(unsigned*)&t;
}
__device__ __forceinline__ float bflo(float x) {
    __nv_bfloat16 h = __float2bfloat16(x);
    return x - __bfloat162float(h);
}
__device__ __forceinline__ u16 bfh(float x) {
    __nv_bfloat16 h = __float2bfloat16(x);
    return *(u16*)&h;
}

// ---------------- weight pre-split ----------------
__global__ void wsplit(const float* __restrict__ W, u16* __restrict__ Wh,
                       u16* __restrict__ Wl, int n) {
    int i = blockIdx.x*256 + threadIdx.x;
    if (i >= n) return;
    float v = W[i];
    Wh[i] = bfh(v);
    Wl[i] = bfh(bflo(v));
}

// ---------------- mask compaction ----------------
__global__ void mask_compact(const int* __restrict__ s, int* __restrict__ sidx, int* __restrict__ cnt) {
    int b = blockIdx.x;
    int tid = threadIdx.x;
    int i = tid >> 4, j = tid & 15;
    int act = (s[b*65536 + (i*17)*256 + j*17] > 0) ? 1 : 0;
    __shared__ int sh[256];
    sh[tid] = act;
    __syncthreads();
    for (int off = 1; off < 256; off <<= 1) {
        int v = (tid >= off) ? sh[tid - off] : 0;
        __syncthreads();
        sh[tid] += v;
        __syncthreads();
    }
    if (act) sidx[b*260 + sh[tid]] = tid + 1;
    if (tid == 255) cnt[b] = sh[255] + 1;
    if (tid == 0) sidx[b*260] = 0;
}

// ---------------- cst_pool + corr column compaction, emitting bf16 hi/lo planes ----------------
__global__ void pool_compact(const float* __restrict__ in,
                             u16* __restrict__ poolh, u16* __restrict__ pooll,
                             u16* __restrict__ corrh, u16* __restrict__ corrl,
                             const int* __restrict__ sidx, const int* __restrict__ cnt) {
    __shared__ float row[8][260];
    int wid = threadIdx.x >> 5, lane = threadIdx.x & 31;
    long r = (long)blockIdx.x*8 + wid;
    int b  = (int)(r / (CIN*TQ));
    int cq = (int)(r % (CIN*TQ));
    const float* src = in + r*TS;
    for (int i = lane; i < TS; i += 32) row[wid][i] = src[i];
    __syncwarp();
    u16* dh = poolh + r*TD;
    u16* dl = pooll + r*TD;
    if (lane == 0) {
        float v = row[wid][0];
        dh[0] = bfh(v); dl[0] = bfh(bflo(v));
    }
    #pragma unroll
    for (int t = lane; t < 64; t += 32) {
        int i = t >> 3, j = t & 7;
        const float* p = &row[wid][1 + i*32 + j*2];
        float v = 0.25f*(p[0] + p[1] + p[16] + p[17]);
        dh[1 + t] = bfh(v); dl[1 + t] = bfh(bflo(v));
    }
    int nact = cnt[b];
    int npad4 = (nact + 3) & ~3;
    const int* sb = sidx + b*260;
    int c = cq / TQ, q = cq % TQ;
    long co = (long)b*CIN*TQ*260 + (long)c*TQ*npad4 + (long)q*npad4;
    for (int j = lane; j < npad4; j += 32) {
        float v = (j < nact) ? row[wid][sb[j]] : 0.f;
        corrh[co + j] = bfh(v);
        corrl[co + j] = bfh(bflo(v));
    }
}

// ---------------- mma macros ----------------
#define LDMX4(r0,r1,r2,r3,addr) \
    asm volatile("ldmatrix.sync.aligned.m8n8.x4.shared.b16 {%0,%1,%2,%3}, [%4];" \
        : "=r"(r0),"=r"(r1),"=r"(r2),"=r"(r3) : "r"(addr))
#define LDMX2T(r0,r1,addr) \
    asm volatile("ldmatrix.sync.aligned.m8n8.x2.trans.shared.b16 {%0,%1}, [%2];" \
        : "=r"(r0),"=r"(r1) : "r"(addr))
#define MMA16816(c0,c1,c2,c3,a0,a1,a2,a3,b0,b1) \
    asm volatile("mma.sync.aligned.m16n8k16.row.col.f32.bf16.bf16.f32 " \
        "{%0,%1,%2,%3}, {%4,%5,%6,%7}, {%8,%9}, {%0,%1,%2,%3};" \
        : "+f"(c0),"+f"(c1),"+f"(c2),"+f"(c3) \
        : "r"(a0),"r"(a1),"r"(a2),"r"(a3),"r"(b0),"r"(b1))

// ---------------- tensor-core GEMM body (3-term bf16 split, pre-split A) ----------------
#define STRA 24
#define STRX 136
#define ABUF (128*STRA)
#define XBUF (16*STRX)
#define BUFSZ (2*ABUF + 2*XBUF)

__device__ __forceinline__ float4 xform4(float4 v, int k, const float* stats,
                                         const float* w, const float* bv) {
    float mu = stats[(k>>6)*2], iv = stats[(k>>6)*2 + 1];
    float ww = w[k]*iv;
    float of = fmaf(-mu, ww, bv[k]);
    v.x = fmaxf(fmaf(v.x, ww, of), 0.f);
    v.y = fmaxf(fmaf(v.y, ww, of), 0.f);
    v.z = fmaxf(fmaf(v.z, ww, of), 0.f);
    v.w = fmaxf(fmaf(v.w, ww, of), 0.f);
    return v;
}

template<bool XBF, bool XF, bool STATS>
__device__ __forceinline__ void gemm_body(
    const u16* __restrict__ Agh, const u16* __restrict__ Agl,
    const float* __restrict__ bias,
    const float* __restrict__ Xf,
    const u16* __restrict__ Xgh, const u16* __restrict__ Xgl,
    float* __restrict__ Yb,
    int m0, int n0, int N, int K, u16* sm_,
    const float* xfStats, const float* xfW, const float* xfB,
    float* partial, int pIdx) {

    int tid = threadIdx.x;
    int wid = tid >> 5, lane = tid & 31;
    int warp_m = wid & 1, warp_n = wid >> 1;

    int arow = tid >> 1, aq = tid & 1;
    const u16* Aph = Agh + (long)(m0 + arow)*K + aq*8;
    const u16* Apl = Agl + (long)(m0 + arow)*K + aq*8;
    int xk = tid >> 4, xn = (tid & 15)*4;
    const float* Xp  = XBF ? nullptr : Xf + (long)xk*N + n0 + xn;
    const u16*   Xph = XBF ? Xgh + (long)xk*N + n0 + xn : nullptr;
    const u16*   Xpl = XBF ? Xgl + (long)xk*N + n0 + xn : nullptr;

    int a_mrow = (lane & 7) + ((lane >> 3) & 1)*8;
    int a_koff = ((lane >> 4) & 1)*8;
    int b_krow = lane & 15;

    float acc[4][4][4];
    #pragma unroll
    for (int i = 0; i < 4; i++)
        #pragma unroll
        for (int j = 0; j < 4; j++)
            #pragma unroll
            for (int r = 0; r < 4; r++) acc[i][j][r] = 0.f;

    int nt_chunks = K >> 4;
    {
        uint4 rah = *(const uint4*)Aph;
        uint4 ral = *(const uint4*)Apl;
        u16* Ah = sm_;
        u16* Al = Ah + ABUF;
        u16* Xh = Ah + 2*ABUF;
        u16* Xl = Xh + XBUF;
        *(uint4*)&Ah[arow*STRA + aq*8] = rah;
        *(uint4*)&Al[arow*STRA + aq*8] = ral;
        if (XBF) {
            *(uint2*)&Xh[xk*STRX + xn]      = *(const uint2*)Xph;
            *(uint2*)&Xh[xk*STRX + xn + 64] = *(const uint2*)(Xph + 64);
            *(uint2*)&Xl[xk*STRX + xn]      = *(const uint2*)Xpl;
            *(uint2*)&Xl[xk*STRX + xn + 64] = *(const uint2*)(Xpl + 64);
        } else {
            float4 x0 = *(const float4*)Xp;
            float4 x1 = *(const float4*)(Xp + 64);
            if (XF) { x0 = xform4(x0, xk, xfStats, xfW, xfB); x1 = xform4(x1, xk, xfStats, xfW, xfB); }
            *(uint2*)&Xh[xk*STRX + xn]      = make_uint2(pk2(x0.x,x0.y), pk2(x0.z,x0.w));
            *(uint2*)&Xh[xk*STRX + xn + 64] = make_uint2(pk2(x1.x,x1.y), pk2(x1.z,x1.w));
            *(uint2*)&Xl[xk*STRX + xn]      = make_uint2(pk2(bflo(x0.x),bflo(x0.y)), pk2(bflo(x0.z),bflo(x0.w)));
            *(uint2*)&Xl[xk*STRX + xn + 64] = make_uint2(pk2(bflo(x1.x),bflo(x1.y)), pk2(bflo(x1.z),bflo(x1.w)));
        }
    }
    __syncthreads();

    for (int t = 0; t < nt_chunks; t++) {
        int cur = t & 1;
        uint4 rah, ral;
        uint2 xh0, xh1, xl0, xl1;
        float4 x0, x1;
        if (t + 1 < nt_chunks) {
            rah = *(const uint4*)(Aph + (t+1)*16);
            ral = *(const uint4*)(Apl + (t+1)*16);
            if (XBF) {
                xh0 = *(const uint2*)(Xph + (long)(t+1)*16*N);
                xh1 = *(const uint2*)(Xph + (long)(t+1)*16*N + 64);
                xl0 = *(const uint2*)(Xpl + (long)(t+1)*16*N);
                xl1 = *(const uint2*)(Xpl + (long)(t+1)*16*N + 64);
            } else {
                x0 = *(const float4*)(Xp + (long)(t+1)*16*N);
                x1 = *(const float4*)(Xp + (long)(t+1)*16*N + 64);
                if (XF) {
                    int k = (t+1)*16 + xk;
                    x0 = xform4(x0, k, xfStats, xfW, xfB);
                    x1 = xform4(x1, k, xfStats, xfW, xfB);
                }
            }
        }

        const u16* Ah = sm_ + cur*BUFSZ;
        const u16* Al = Ah + ABUF;
        const u16* Xh = Ah + 2*ABUF;
        const u16* Xl = Xh + XBUF;

        unsigned bh[4][2], bl[4][2];
        #pragma unroll
        for (int nt = 0; nt < 4; nt++) {
            int col = warp_n*32 + nt*8;
            unsigned ad = (unsigned)__cvta_generic_to_shared(&Xh[b_krow*STRX + col]);
            LDMX2T(bh[nt][0], bh[nt][1], ad);
            ad = (unsigned)__cvta_generic_to_shared(&Xl[b_krow*STRX + col]);
            LDMX2T(bl[nt][0], bl[nt][1], ad);
        }

        #pragma unroll
        for (int mt = 0; mt < 4; mt++) {
            int row = warp_m*64 + mt*16 + a_mrow;
            unsigned ah0,ah1,ah2,ah3, al0,al1,al2,al3;
            unsigned ad = (unsigned)__cvta_generic_to_shared(&Ah[row*STRA + a_koff]);
            LDMX4(ah0,ah1,ah2,ah3, ad);
            ad = (unsigned)__cvta_generic_to_shared(&Al[row*STRA + a_koff]);
            LDMX4(al0,al1,al2,al3, ad);
            #pragma unroll
            for (int nt = 0; nt < 4; nt++) {
                float* c = acc[mt][nt];
                MMA16816(c[0],c[1],c[2],c[3], ah0,ah1,ah2,ah3, bh[nt][0],bh[nt][1]);
                MMA16816(c[0],c[1],c[2],c[3], ah0,ah1,ah2,ah3, bl[nt][0],bl[nt][1]);
                MMA16816(c[0],c[1],c[2],c[3], al0,al1,al2,al3, bh[nt][0],bh[nt][1]);
            }
        }

        if (t + 1 < nt_chunks) {
            int nxt = cur ^ 1;
            u16* Ah2 = sm_ + nxt*BUFSZ;
            u16* Al2 = Ah2 + ABUF;
            u16* Xh2 = Ah2 + 2*ABUF;
            u16* Xl2 = Xh2 + XBUF;
            *(uint4*)&Ah2[arow*STRA + aq*8] = rah;
            *(uint4*)&Al2[arow*STRA + aq*8] = ral;
            if (XBF) {
                *(uint2*)&Xh2[xk*STRX + xn]      = xh0;
                *(uint2*)&Xh2[xk*STRX + xn + 64] = xh1;
                *(uint2*)&Xl2[xk*STRX + xn]      = xl0;
                *(uint2*)&Xl2[xk*STRX + xn + 64] = xl1;
            } else {
                *(uint2*)&Xh2[xk*STRX + xn]      = make_uint2(pk2(x0.x,x0.y), pk2(x0.z,x0.w));
                *(uint2*)&Xh2[xk*STRX + xn + 64] = make_uint2(pk2(x1.x,x1.y), pk2(x1.z,x1.w));
                *(uint2*)&Xl2[xk*STRX + xn]      = make_uint2(pk2(bflo(x0.x),bflo(x0.y)), pk2(bflo(x0.z),bflo(x0.w)));
                *(uint2*)&Xl2[xk*STRX + xn + 64] = make_uint2(pk2(bflo(x1.x),bflo(x1.y)), pk2(bflo(x1.z),bflo(x1.w)));
            }
            __syncthreads();
        }
    }

    int g = lane >> 2, tq = lane & 3;
    float s1 = 0.f, s2 = 0.f;
    #pragma unroll
    for (int mt = 0; mt < 4; mt++) {
        int r0 = m0 + warp_m*64 + mt*16 + g;
        float b0v = bias ? bias[r0]   : 0.f;
        float b1v = bias ? bias[r0+8] : 0.f;
        #pragma unroll
        for (int nt = 0; nt < 4; nt++) {
            int c = n0 + warp_n*32 + nt*8 + tq*2;
            float* a = acc[mt][nt];
            float v0 = a[0]+b0v, v1 = a[1]+b0v, v2 = a[2]+b1v, v3 = a[3]+b1v;
            *(float2*)&Yb[(long)r0*N + c]     = make_float2(v0, v1);
            *(float2*)&Yb[(long)(r0+8)*N + c] = make_float2(v2, v3);
            if (STATS) {
                s1 += v0 + v1 + v2 + v3;
                s2 += v0*v0 + v1*v1 + v2*v2 + v3*v3;
            }
        }
    }
    if (STATS) {
        __syncthreads();
        float* red = (float*)sm_;
        red[tid] = s1; red[tid + 256] = s2;
        __syncthreads();
        for (int o = 128; o > 0; o >>= 1) {
            if (tid < o) { red[tid] += red[tid+o]; red[tid+256] += red[tid+256+o]; }
            __syncthreads();
        }
        if (tid == 0) {
            partial[pIdx*2 + 0] = red[0];
            partial[pIdx*2 + 1] = red[256];
        }
    }
}

__global__ void __launch_bounds__(256, 2)
gemm_agg(const u16* __restrict__ Agh, const u16* __restrict__ Agl,
         const float* __restrict__ X, float* __restrict__ Y,
         int M, int N, int K,
         const float* __restrict__ xfStats, const float* __restrict__ xfW,
         const float* __restrict__ xfB, float* __restrict__ partial) {
    __shared__ __align__(16) u16 sm_[2*BUFSZ];
    int b = blockIdx.z;
    int pIdx = (b*gridDim.y + blockIdx.y)*gridDim.x + blockIdx.x;
    gemm_body<false,true,true>(Agh, Agl, nullptr, X + (long)b*K*N, nullptr, nullptr,
                               Y + (long)b*M*N, blockIdx.y*128, blockIdx.x*128, N, K, sm_,
                               xfStats + b*8, xfW, xfB, partial, pIdx);
}

__global__ void __launch_bounds__(256, 2)
gemm_qres(const u16* __restrict__ Wqh, const u16* __restrict__ Wql,
          const float* __restrict__ bq,
          const u16* __restrict__ Wsh, const u16* __restrict__ Wsl,
          const u16* __restrict__ Xh, const u16* __restrict__ Xl,
          float* __restrict__ Yq, float* __restrict__ Yres,
          float* __restrict__ partial, int N, int K) {
    __shared__ __align__(16) u16 sm_[2*BUFSZ];
    int b = blockIdx.z;
    const u16* xh = Xh + (long)b*K*N;
    const u16* xl = Xl + (long)b*K*N;
    if (blockIdx.y < 2) {
        gemm_body<true,false,false>(Wqh, Wql, bq, nullptr, xh, xl,
                                    Yq + (long)b*HID*N, blockIdx.y*128, blockIdx.x*128, N, K, sm_,
                                    nullptr, nullptr, nullptr, nullptr, 0);
    } else {
        int pIdx = (b*4 + (blockIdx.y - 2))*gridDim.x + blockIdx.x;
        gemm_body<true,false,true>(Wsh, Wsl, nullptr, nullptr, xh, xl,
                                   Yres + (long)b*COUT*N, (blockIdx.y - 2)*128, blockIdx.x*128, N, K, sm_,
                                   nullptr, nullptr, nullptr, partial, pIdx);
    }
}

__global__ void __launch_bounds__(256, 2)
gemm_kv(const u16* __restrict__ Wh, const u16* __restrict__ Wl,
        const float* __restrict__ bias,
        const u16* __restrict__ Xh, const u16* __restrict__ Xl,
        float* __restrict__ Y, int K, const int* __restrict__ cnt) {
    __shared__ __align__(16) u16 sm_[2*BUFSZ];
    int b = blockIdx.z;
    int nact = cnt[b];
    int npad4 = (nact + 3) & ~3;
    int N = TQ*npad4;
    int n0 = blockIdx.x*128;
    if (n0 >= N) return;
    gemm_body<true,false,false>(Wh, Wl, bias, nullptr,
                                Xh + (long)b*CIN*TQ*260, Xl + (long)b*CIN*TQ*260,
                                Y + (long)b*2*HID*TQ*260,
                                blockIdx.y*128, n0, N, K, sm_,
                                nullptr, nullptr, nullptr, nullptr, 0);
}

// ---------------- GroupNorm kernels ----------------
__global__ void gn_finalize(const float* __restrict__ partial, float* __restrict__ stats,
                            int nb, float invN) {
    int bg = threadIdx.x;
    if (bg >= 16) return;
    float s1 = 0.f, s2 = 0.f;
    for (int i = 0; i < nb; i++) {
        s1 += partial[(bg*nb + i)*2 + 0];
        s2 += partial[(bg*nb + i)*2 + 1];
    }
    float mean = s1*invN;
    float var  = fmaxf(s2*invN - mean*mean, 0.f);
    stats[bg*2 + 0] = mean;
    stats[bg*2 + 1] = 1.0f/sqrtf(var + 1e-5f);
}

__global__ void gn_apply(const float* __restrict__ x, float* __restrict__ out,
                         const float* __restrict__ w, const float* __restrict__ bvec,
                         const float* __restrict__ stats,
                         long groupSize, int T, int C, long n4) {
    long i4 = (long)blockIdx.x*blockDim.x + threadIdx.x;
    if (i4 >= n4) return;
    long e = i4*4;
    int bg = (int)(e / groupSize);
    int c  = (int)((e / T) % C);
    float mu = stats[bg*2], iv = stats[bg*2 + 1];
    float ww = w[c]*iv;
    float of = fmaf(-mu, ww, bvec[c]);
    float4 v = ((const float4*)x)[i4];
    v.x = fmaf(v.x, ww, of);
    v.y = fmaf(v.y, ww, of);
    v.z = fmaf(v.z, ww, of);
    v.w = fmaf(v.w, ww, of);
    ((float4*)out)[i4] = v;
}

__global__ void gn_fuse2(const float* __restrict__ agg, float* __restrict__ res_t,
                         const float* __restrict__ w2, const float* __restrict__ b2,
                         const float* __restrict__ wsc, const float* __restrict__ bsc,
                         const float* __restrict__ stats2, const float* __restrict__ statssc,
                         float* __restrict__ partial,
                         long groupSize, int T, int C) {
    long bg = blockIdx.y;
    long base4 = bg*(groupSize >> 2);
    float mu2 = stats2[bg*2],  inv2 = stats2[bg*2 + 1];
    float mus = statssc[bg*2], invs = statssc[bg*2 + 1];
    int tid = threadIdx.x;
    long gs4 = groupSize >> 2;
    float s1 = 0.f, s2 = 0.f;
    for (long i = (long)blockIdx.x*blockDim.x + tid; i < gs4; i += (long)gridDim.x*blockDim.x) {
        long i4 = base4 + i;
        long e = i4*4;
        int c = (int)((e / T) % C);
        float wa = w2[c]*inv2,  oa = fmaf(-mu2, wa, b2[c]);
        float wr = wsc[c]*invs, orr = fmaf(-mus, wr, bsc[c]);
        float4 a = ((const float4*)agg)[i4];
        float4 r = ((const float4*)res_t)[i4];
        float4 v;
        v.x = fmaxf(fmaf(a.x, wa, oa), 0.f) + fmaxf(fmaf(r.x, wr, orr), 0.f);
        v.y = fmaxf(fmaf(a.y, wa, oa), 0.f) + fmaxf(fmaf(r.y, wr, orr), 0.f);
        v.z = fmaxf(fmaf(a.z, wa, oa), 0.f) + fmaxf(fmaf(r.z, wr, orr), 0.f);
        v.w = fmaxf(fmaf(a.w, wa, oa), 0.f) + fmaxf(fmaf(r.w, wr, orr), 0.f);
        ((float4*)res_t)[i4] = v;
        s1 += v.x + v.y + v.z + v.w;
        s2 += v.x*v.x + v.y*v.y + v.z*v.z + v.w*v.w;
    }
    __shared__ float sh1[256], sh2[256];
    sh1[tid] = s1; sh2[tid] = s2;
    __syncthreads();
    for (int o = 128; o > 0; o >>= 1) {
        if (tid < o) { sh1[tid] += sh1[tid+o]; sh2[tid] += sh2[tid+o]; }
        __syncthreads();
    }
    if (tid == 0) {
        partial[(bg*gridDim.x + blockIdx.x)*2 + 0] = sh1[0];
        partial[(bg*gridDim.x + blockIdx.x)*2 + 1] = sh2[0];
    }
}

// ---------------- fused attention: V prefetched into its own buffer ----------------
#define SM_Q   (32*68)
#define SM_K   (32*260)
#define SM_S   (68*260)
#define SMEM_FLOATS (SM_Q + 2*SM_K + SM_S)
#define SMEM_BYTES  (SMEM_FLOATS*4)

__global__ void attn_kernel(const float* __restrict__ gq, const float* __restrict__ gkv,
                            const int* __restrict__ cnt, float* __restrict__ gout,
                            float* __restrict__ partial1) {
    extern __shared__ float sm[];
    float* Qs = sm;
    float* Ks = Qs + SM_Q;
    float* Vs = Ks + SM_K;
    float* S  = Vs + SM_K;
    __shared__ float Sinv[68];
    __shared__ float red1[256], red2[256];

    int q = blockIdx.x, g = blockIdx.y, b = blockIdx.z;
    int tid = threadIdx.x;
    int wid = tid >> 5, lane = tid & 31;
    long qbase = ((long)(b*HID + g*EDIM)*TQ + q)*TD;

    int nact  = cnt[b];
    int npad  = (nact + 3) & ~3;
    int ntile = npad >> 2;
    long kvs  = (long)TQ*npad;
    const float* kptr = gkv + (long)b*2*HID*TQ*260 + (long)(g*EDIM)*kvs + (long)q*npad;
    const float* vptr = kptr + (long)HID*kvs;

    // Issue ALL global loads up front: Q, K, then V into its own buffer.
    // V's latency hides under the S-phase compute.
    for (int i = tid; i < SM_Q; i += 256) {
        int e = i/68, d = i%68;
        Qs[i] = (d < TD) ? gq[qbase + (long)e*TQ*TD + d] : 0.f;
    }
    for (int e = wid; e < 32; e += 8) {
        const float* kp = kptr + (long)e*kvs;
        for (int j4 = lane; j4 < ntile; j4 += 32)
            *(float4*)&Ks[e*260 + j4*4] = *(const float4*)(kp + j4*4);
    }
    for (int e = wid; e < 32; e += 8) {
        const float* vp = vptr + (long)e*kvs;
        for (int j4 = lane; j4 < ntile; j4 += 32)
            *(float4*)&Vs[e*260 + j4*4] = *(const float4*)(vp + j4*4);
    }
    __syncthreads();

    // S[d][j] = sum_e Q[e][d]*K[e][j]
    int ntt = 17*ntile;
    for (int t = tid; t < ntt; t += 256) {
        int dt = t/ntile, st = t%ntile;
        float acc[4][4];
        #pragma unroll
        for (int i = 0; i < 4; i++)
            #pragma unroll
            for (int j = 0; j < 4; j++) acc[i][j] = 0.f;
        #pragma unroll
        for (int e = 0; e < 32; e++) {
            float4 a  = *(const float4*)&Qs[e*68 + dt*4];
            float4 k4 = *(const float4*)&Ks[e*260 + st*4];
            acc[0][0] += a.x*k4.x; acc[0][1] += a.x*k4.y; acc[0][2] += a.x*k4.z; acc[0][3] += a.x*k4.w;
            acc[1][0] += a.y*k4.x; acc[1][1] += a.y*k4.y; acc[1][2] += a.y*k4.z; acc[1][3] += a.y*k4.w;
            acc[2][0] += a.z*k4.x; acc[2][1] += a.z*k4.y; acc[2][2] += a.z*k4.z; acc[2][3] += a.z*k4.w;
            acc[3][0] += a.w*k4.x; acc[3][1] += a.w*k4.y; acc[3][2] += a.w*k4.z; acc[3][3] += a.w*k4.w;
        }
        #pragma unroll
        for (int i = 0; i < 4; i++)
            #pragma unroll
            for (int j = 0; j < 4; j++)
                S[(dt*4 + i)*260 + st*4 + j] = acc[i][j];
    }
    __syncthreads();

    // softmax (single pass; logits bounded so no max-subtraction needed)
    for (int d = wid; d < TD; d += 8) {
        float sum = 0.f;
        for (int j = lane; j < nact; j += 32) {
            float e = fexp(S[d*260 + j]);
            S[d*260 + j] = e;
            sum += e;
        }
        #pragma unroll
        for (int o = 16; o > 0; o >>= 1) sum += __shfl_xor_sync(0xffffffffu, sum, o);
        if (lane == 0) Sinv[d] = 1.0f/sum;
        if (lane < npad - nact) S[d*260 + nact + lane] = 0.f;
    }
    __syncthreads();

    // O-phase main: 128 tasks (8 et x 16 dt, d<64) x 2 halves = 256 items, ONE round.
    long obase = qbase;
    int halfTiles = (ntile + 1) >> 1;
    float s1 = 0.f, s2 = 0.f;
    {
        int task = tid >> 1, half = tid & 1;
        int et = task >> 4, dt = task & 15;
        float acc[4][4];
        #pragma unroll
        for (int j = 0; j < 4; j++)
            #pragma unroll
            for (int i = 0; i < 4; i++) acc[j][i] = 0.f;
        int sA = half*halfTiles;
        int sB = min(ntile, sA + halfTiles);
        for (int s4 = sA; s4 < sB; s4++) {
            float4 a0 = *(const float4*)&S[(dt*4 + 0)*260 + s4*4];
            float4 a1 = *(const float4*)&S[(dt*4 + 1)*260 + s4*4];
            float4 a2 = *(const float4*)&S[(dt*4 + 2)*260 + s4*4];
            float4 a3 = *(const float4*)&S[(dt*4 + 3)*260 + s4*4];
            float4 v0 = *(const float4*)&Vs[(et*4 + 0)*260 + s4*4];
            float4 v1 = *(const float4*)&Vs[(et*4 + 1)*260 + s4*4];
            float4 v2 = *(const float4*)&Vs[(et*4 + 2)*260 + s4*4];
            float4 v3 = *(const float4*)&Vs[(et*4 + 3)*260 + s4*4];
            acc[0][0] += a0.x*v0.x + a0.y*v0.y + a0.z*v0.z + a0.w*v0.w;
            acc[0][1] += a1.x*v0.x + a1.y*v0.y + a1.z*v0.z + a1.w*v0.w;
            acc[0][2] += a2.x*v0.x + a2.y*v0.y + a2.z*v0.z + a2.w*v0.w;
            acc[0][3] += a3.x*v0.x + a3.y*v0.y + a3.z*v0.z + a3.w*v0.w;
            acc[1][0] += a0.x*v1.x + a0.y*v1.y + a0.z*v1.z + a0.w*v1.w;
            acc[1][1] += a1.x*v1.x + a1.y*v1.y + a1.z*v1.z + a1.w*v1.w;
            acc[1][2] += a2.x*v1.x + a2.y*v1.y + a2.z*v1.z + a2.w*v1.w;
            acc[1][3] += a3.x*v1.x + a3.y*v1.y + a3.z*v1.z + a3.w*v1.w;
            acc[2][0] += a0.x*v2.x + a0.y*v2.y + a0.z*v2.z + a0.w*v2.w;
            acc[2][1] += a1.x*v2.x + a1.y*v2.y + a1.z*v2.z + a1.w*v2.w;
            acc[2][2] += a2.x*v2.x + a2.y*v2.y + a2.z*v2.z + a2.w*v2.w;
            acc[2][3] += a3.x*v2.x + a3.y*v2.y + a3.z*v2.z + a3.w*v2.w;
            acc[3][0] += a0.x*v3.x + a0.y*v3.y + a0.z*v3.z + a0.w*v3.w;
            acc[3][1] += a1.x*v3.x + a1.y*v3.y + a1.z*v3.z + a1.w*v3.w;
            acc[3][2] += a2.x*v3.x + a2.y*v3.y + a2.z*v3.z + a2.w*v3.w;
            acc[3][3] += a3.x*v3.x + a3.y*v3.y + a3.z*v3.z + a3.w*v3.w;
        }
        #pragma unroll
        for (int j = 0; j < 4; j++)
            #pragma unroll
            for (int i = 0; i < 4; i++)
                acc[j][i] += __shfl_xor_sync(0xffffffffu, acc[j][i], 1);
        if (half == 0) {
            #pragma unroll
            for (int j = 0; j < 4; j++)
                #pragma unroll
                for (int i = 0; i < 4; i++) {
                    int d = dt*4 + i;
                    float v = acc[j][i]*Sinv[d];
                    gout[obase + (long)(et*4 + j)*TQ*TD + d] = v;
                    s1 += v; s2 += v*v;
                }
        }
    }
    // O-phase tail: d=64 column
    {
        int e = tid >> 3, oct = tid & 7;
        int octTiles = (ntile + 7) >> 3;
        int sA = oct*octTiles;
        int sB = min(ntile, sA + octTiles);
        float a = 0.f;
        for (int s4 = sA; s4 < sB; s4++) {
            float4 sv = *(const float4*)&S[64*260 + s4*4];
            float4 vv = *(const float4*)&Vs[e*260 + s4*4];
            a += sv.x*vv.x + sv.y*vv.y + sv.z*vv.z + sv.w*vv.w;
        }
        a += __shfl_xor_sync(0xffffffffu, a, 1);
        a += __shfl_xor_sync(0xffffffffu, a, 2);
        a += __shfl_xor_sync(0xffffffffu, a, 4);
        if (oct == 0) {
            float v = a*Sinv[64];
            gout[obase + (long)e*TQ*TD + 64] = v;
            s1 += v; s2 += v*v;
        }
    }

    red1[tid] = s1; red2[tid] = s2;
    __syncthreads();
    for (int o = 128; o > 0; o >>= 1) {
        if (tid < o) { red1[tid] += red1[tid+o]; red2[tid] += red2[tid+o]; }
        __syncthreads();
    }
    if (tid == 0) {
        int pIdx = (b*4 + (g >> 1))*512 + (g & 1)*256 + q;
        partial1[pIdx*2 + 0] = red1[0];
        partial1[pIdx*2 + 1] = red2[0];
    }
}

// ---------------- host orchestration ----------------
extern "C" void kernel_launch(void* const* d_in, const int* in_sizes, int n_in,
                              void* d_out, int out_size) {
    const float* corr   = (const float*)d_in[0];
    const int*   smask  = (const int*)  d_in[1];
    const float* W_sc   = (const float*)d_in[2];
    const float* gnscw  = (const float*)d_in[3];
    const float* gnscb  = (const float*)d_in[4];
    const float* W_qkv  = (const float*)d_in[5];
    const float* b_qkv  = (const float*)d_in[6];
    const float* gn1w   = (const float*)d_in[7];
    const float* gn1b   = (const float*)d_in[8];
    const float* W_agg  = (const float*)d_in[9];
    const float* gn2w   = (const float*)d_in[10];
    const float* gn2b   = (const float*)d_in[11];
    const float* gnow   = (const float*)d_in[12];
    const float* gnob   = (const float*)d_in[13];
    float* out = (float*)d_out;

    u16 *poolh, *pooll, *corrh, *corrl, *wqkvh, *wqkvl, *wsch, *wscl, *waggh, *waggl;
    float *kv, *q, *res, *att, *agg;
    float *partial, *partial1, *stats, *stats_sc, *stats1, *stats2;
    int *sidx, *cnt;
    cudaGetSymbolAddress((void**)&poolh,   g_pooledh);
    cudaGetSymbolAddress((void**)&pooll,   g_pooledl);
    cudaGetSymbolAddress((void**)&corrh,   g_corrch);
    cudaGetSymbolAddress((void**)&corrl,   g_corrcl);
    cudaGetSymbolAddress((void**)&wqkvh,   g_wqkvh);
    cudaGetSymbolAddress((void**)&wqkvl,   g_wqkvl);
    cudaGetSymbolAddress((void**)&wsch,    g_wsch);
    cudaGetSymbolAddress((void**)&wscl,    g_wscl);
    cudaGetSymbolAddress((void**)&waggh,   g_waggh);
    cudaGetSymbolAddress((void**)&waggl,   g_waggl);
    cudaGetSymbolAddress((void**)&kv,      g_kv);
    cudaGetSymbolAddress((void**)&q,       g_q);
    cudaGetSymbolAddress((void**)&res,     g_res);
    cudaGetSymbolAddress((void**)&att,     g_att);
    cudaGetSymbolAddress((void**)&agg,     g_agg);
    cudaGetSymbolAddress((void**)&sidx,    g_sidx);
    cudaGetSymbolAddress((void**)&cnt,     g_cnt);
    cudaGetSymbolAddress((void**)&partial, g_partial);
    cudaGetSymbolAddress((void**)&partial1,g_partial1);
    cudaGetSymbolAddress((void**)&stats,   g_stats);
    cudaGetSymbolAddress((void**)&stats_sc,g_stats_sc);
    cudaGetSymbolAddress((void**)&stats1,  g_stats1);
    cudaGetSymbolAddress((void**)&stats2,  g_stats2);

    const int NPOOL = TQ*TD;     // 16640
    const int NKVMAX = TQ*260;   // 66560

    const long gsC = (long)(COUT/4)*NPOOL;
    const long gsH = (long)(HID/4)*NPOOL;
    const float invC = 1.0f/(float)gsC;
    const float invH = 1.0f/(float)gsH;

    // 0. weight pre-split (tiny)
    wsplit<<<(768*CIN + 255)/256, 256>>>(W_qkv, wqkvh, wqkvl, 768*CIN);
    wsplit<<<(COUT*CIN + 255)/256, 256>>>(W_sc,  wsch,  wscl,  COUT*CIN);
    wsplit<<<(COUT*HID + 255)/256, 256>>>(W_agg, waggh, waggl, COUT*HID);

    // 1. mask compaction, pool + compact (bf16 hi/lo planes)
    mask_compact<<<BB, 256>>>(smask, sidx, cnt);
    pool_compact<<<BB*CIN*TQ/8, 256>>>(corr, poolh, pooll, corrh, corrl, sidx, cnt);

    // 2. GEMMs
    gemm_qres<<<dim3(NPOOL/128, 6, BB), 256>>>(wqkvh, wqkvl, b_qkv, wsch, wscl,
                                               poolh, pooll, q, res, partial, NPOOL, CIN);
    gemm_kv<<<dim3(NKVMAX/128, 2*HID/128, BB), 256>>>(wqkvh + HID*CIN, wqkvl + HID*CIN,
                                                      b_qkv + HID, corrh, corrl, kv, CIN, cnt);
    gn_finalize<<<1, 16>>>(partial, stats_sc, 130, invC);

    // 3. attention (V prefetched)
    cudaFuncSetAttribute(attn_kernel, cudaFuncAttributeMaxDynamicSharedMemorySize, SMEM_BYTES);
    attn_kernel<<<dim3(TQ, NHEAD, BB), 256, SMEM_BYTES>>>(q, kv, cnt, att, partial1);
    gn_finalize<<<1, 16>>>(partial1, stats1, 512, invH);

    // 4. agg = W_agg @ relu(gn1(att)), gn1 fused in loader; emits gn2 partials
    gemm_agg<<<dim3(NPOOL/128, COUT/128, BB), 256>>>(waggh, waggl, att, agg, COUT, NPOOL, HID,
                                                     stats1, gn1w, gn1b, partial);
    gn_finalize<<<1, 16>>>(partial, stats2, 130, invC);

    // 5. fuse + gn_out
    gn_fuse2<<<dim3(128, 16), 256>>>(agg, res, gn2w, gn2b, gnscw, gnscb,
                                     stats2, stats_sc, partial, gsC, NPOOL, COUT);
    gn_finalize<<<1, 16>>>(partial, stats, 128, invC);
    {
        long n4 = ((long)BB*COUT*NPOOL) >> 2;
        gn_apply<<<(unsigned)((n4 + 255)/256), 256>>>(res, out, gnow, gnob, stats, gsC, NPOOL, COUT, n4);
    }
}

// round 17
// speedup vs baseline: 1.3322x; 1.3322x over previous
#include <cuda_runtime.h>
#include <cuda_bf16.h>
#include <math.h>

#define BB 4
#define CIN 128
#define TQ 256
#define TS 257
#define TD 65
#define HID 256
#define COUT 512
#define NHEAD 8
#define EDIM 32

typedef unsigned short u16;

// ---------------- scratch (static device globals; no allocation) ----------------
__device__ u16   g_pooledh[BB*CIN*TQ*TD];
__device__ u16   g_pooledl[BB*CIN*TQ*TD];
__device__ u16   g_corrch[BB*CIN*TQ*260];
__device__ u16   g_corrcl[BB*CIN*TQ*260];
__device__ u16   g_wqkvh[768*CIN],  g_wqkvl[768*CIN];
__device__ u16   g_wsch[COUT*CIN],  g_wscl[COUT*CIN];
__device__ u16   g_waggh[COUT*HID], g_waggl[COUT*HID];
__device__ float g_kv[BB*2*HID*TQ*260];
__device__ float g_q[BB*HID*TQ*TD];
__device__ float g_res[BB*COUT*TQ*TD];
__device__ float g_att[BB*HID*TQ*TD];
__device__ float g_agg[BB*COUT*TQ*TD];
__device__ int   g_sidx[BB*260];
__device__ int   g_cnt[BB];
__device__ float g_partial[16*130*2];
__device__ float g_partial1[16*512*2];
__device__ float g_stats[16*2];
__device__ float g_stats_sc[16*2];
__device__ float g_stats1[16*2];
__device__ float g_stats2[16*2];

// ---------------- helpers ----------------
__device__ __forceinline__ float fexp(float x) {
    float y = x * 1.44269504f;
    y = fmaxf(y, -126.0f);
    float z = y + 12582912.0f;
    int   r = __float_as_int(z) - 0x4B400000;
    float f = y - (z - 12582912.0f);
    float p =        1.53832606e-4f;
    p = fmaf(p, f, 1.33978284e-3f);
    p = fmaf(p, f, 9.61833310e-3f);
    p = fmaf(p, f, 5.55036624e-2f);
    p = fmaf(p, f, 2.40226500e-1f);
    p = fmaf(p, f, 6.93147182e-1f);
    p = fmaf(p, f, 1.0f);
    return p * __int_as_float((r + 127) << 23);
}
__device__ __forceinline__ unsigned pk2(float x, float y) {
    __nv_bfloat162 t = __floats2bfloat162_rn(x, y);
    return *(unsigned*)&t;
}
__device__ __forceinline__ float bflo(float x) {
    __nv_bfloat16 h = __float2bfloat16(x);
    return x - __bfloat162float(h);
}
__device__ __forceinline__ u16 bfh(float x) {
    __nv_bfloat16 h = __float2bfloat16(x);
    return *(u16*)&h;
}

// ---------------- weight pre-split ----------------
__global__ void wsplit(const float* __restrict__ W, u16* __restrict__ Wh,
                       u16* __restrict__ Wl, int n) {
    int i = blockIdx.x*256 + threadIdx.x;
    if (i >= n) return;
    float v = W[i];
    Wh[i] = bfh(v);
    Wl[i] = bfh(bflo(v));
}

// ---------------- mask compaction ----------------
__global__ void mask_compact(const int* __restrict__ s, int* __restrict__ sidx, int* __restrict__ cnt) {
    int b = blockIdx.x;
    int tid = threadIdx.x;
    int i = tid >> 4, j = tid & 15;
    int act = (s[b*65536 + (i*17)*256 + j*17] > 0) ? 1 : 0;
    __shared__ int sh[256];
    sh[tid] = act;
    __syncthreads();
    for (int off = 1; off < 256; off <<= 1) {
        int v = (tid >= off) ? sh[tid - off] : 0;
        __syncthreads();
        sh[tid] += v;
        __syncthreads();
    }
    if (act) sidx[b*260 + sh[tid]] = tid + 1;
    if (tid == 255) cnt[b] = sh[255] + 1;
    if (tid == 0) sidx[b*260] = 0;
}

// ---------------- cst_pool + corr column compaction, emitting bf16 hi/lo planes ----------------
__global__ void pool_compact(const float* __restrict__ in,
                             u16* __restrict__ poolh, u16* __restrict__ pooll,
                             u16* __restrict__ corrh, u16* __restrict__ corrl,
                             const int* __restrict__ sidx, const int* __restrict__ cnt) {
    __shared__ float row[8][260];
    int wid = threadIdx.x >> 5, lane = threadIdx.x & 31;
    long r = (long)blockIdx.x*8 + wid;
    int b  = (int)(r / (CIN*TQ));
    int cq = (int)(r % (CIN*TQ));
    const float* src = in + r*TS;
    for (int i = lane; i < TS; i += 32) row[wid][i] = src[i];
    __syncwarp();
    u16* dh = poolh + r*TD;
    u16* dl = pooll + r*TD;
    if (lane == 0) {
        float v = row[wid][0];
        dh[0] = bfh(v); dl[0] = bfh(bflo(v));
    }
    #pragma unroll
    for (int t = lane; t < 64; t += 32) {
        int i = t >> 3, j = t & 7;
        const float* p = &row[wid][1 + i*32 + j*2];
        float v = 0.25f*(p[0] + p[1] + p[16] + p[17]);
        dh[1 + t] = bfh(v); dl[1 + t] = bfh(bflo(v));
    }
    int nact = cnt[b];
    int npad4 = (nact + 3) & ~3;
    const int* sb = sidx + b*260;
    int c = cq / TQ, q = cq % TQ;
    long co = (long)b*CIN*TQ*260 + (long)c*TQ*npad4 + (long)q*npad4;
    for (int j = lane; j < npad4; j += 32) {
        float v = (j < nact) ? row[wid][sb[j]] : 0.f;
        corrh[co + j] = bfh(v);
        corrl[co + j] = bfh(bflo(v));
    }
}

// ---------------- mma macros ----------------
#define LDMX4(r0,r1,r2,r3,addr) \
    asm volatile("ldmatrix.sync.aligned.m8n8.x4.shared.b16 {%0,%1,%2,%3}, [%4];" \
        : "=r"(r0),"=r"(r1),"=r"(r2),"=r"(r3) : "r"(addr))
#define LDMX2T(r0,r1,addr) \
    asm volatile("ldmatrix.sync.aligned.m8n8.x2.trans.shared.b16 {%0,%1}, [%2];" \
        : "=r"(r0),"=r"(r1) : "r"(addr))
#define MMA16816(c0,c1,c2,c3,a0,a1,a2,a3,b0,b1) \
    asm volatile("mma.sync.aligned.m16n8k16.row.col.f32.bf16.bf16.f32 " \
        "{%0,%1,%2,%3}, {%4,%5,%6,%7}, {%8,%9}, {%0,%1,%2,%3};" \
        : "+f"(c0),"+f"(c1),"+f"(c2),"+f"(c3) \
        : "r"(a0),"r"(a1),"r"(a2),"r"(a3),"r"(b0),"r"(b1))

// ---------------- tensor-core GEMM body (3-term bf16 split, pre-split A) ----------------
#define STRA 24
#define STRX 136
#define ABUF (128*STRA)
#define XBUF (16*STRX)
#define BUFSZ (2*ABUF + 2*XBUF)

__device__ __forceinline__ float4 xform4(float4 v, int k, const float* stats,
                                         const float* w, const float* bv) {
    float mu = stats[(k>>6)*2], iv = stats[(k>>6)*2 + 1];
    float ww = w[k]*iv;
    float of = fmaf(-mu, ww, bv[k]);
    v.x = fmaxf(fmaf(v.x, ww, of), 0.f);
    v.y = fmaxf(fmaf(v.y, ww, of), 0.f);
    v.z = fmaxf(fmaf(v.z, ww, of), 0.f);
    v.w = fmaxf(fmaf(v.w, ww, of), 0.f);
    return v;
}

template<bool XBF, bool XF, bool STATS>
__device__ __forceinline__ void gemm_body(
    const u16* __restrict__ Agh, const u16* __restrict__ Agl,
    const float* __restrict__ bias,
    const float* __restrict__ Xf,
    const u16* __restrict__ Xgh, const u16* __restrict__ Xgl,
    float* __restrict__ Yb,
    int m0, int n0, int N, int K, u16* sm_,
    const float* xfStats, const float* xfW, const float* xfB,
    float* partial, int pIdx) {

    int tid = threadIdx.x;
    int wid = tid >> 5, lane = tid & 31;
    int warp_m = wid & 1, warp_n = wid >> 1;

    int arow = tid >> 1, aq = tid & 1;
    const u16* Aph = Agh + (long)(m0 + arow)*K + aq*8;
    const u16* Apl = Agl + (long)(m0 + arow)*K + aq*8;
    int xk = tid >> 4, xn = (tid & 15)*4;
    const float* Xp  = XBF ? nullptr : Xf + (long)xk*N + n0 + xn;
    const u16*   Xph = XBF ? Xgh + (long)xk*N + n0 + xn : nullptr;
    const u16*   Xpl = XBF ? Xgl + (long)xk*N + n0 + xn : nullptr;

    int a_mrow = (lane & 7) + ((lane >> 3) & 1)*8;
    int a_koff = ((lane >> 4) & 1)*8;
    int b_krow = lane & 15;

    float acc[4][4][4];
    #pragma unroll
    for (int i = 0; i < 4; i++)
        #pragma unroll
        for (int j = 0; j < 4; j++)
            #pragma unroll
            for (int r = 0; r < 4; r++) acc[i][j][r] = 0.f;

    int nt_chunks = K >> 4;
    {
        uint4 rah = *(const uint4*)Aph;
        uint4 ral = *(const uint4*)Apl;
        u16* Ah = sm_;
        u16* Al = Ah + ABUF;
        u16* Xh = Ah + 2*ABUF;
        u16* Xl = Xh + XBUF;
        *(uint4*)&Ah[arow*STRA + aq*8] = rah;
        *(uint4*)&Al[arow*STRA + aq*8] = ral;
        if (XBF) {
            *(uint2*)&Xh[xk*STRX + xn]      = *(const uint2*)Xph;
            *(uint2*)&Xh[xk*STRX + xn + 64] = *(const uint2*)(Xph + 64);
            *(uint2*)&Xl[xk*STRX + xn]      = *(const uint2*)Xpl;
            *(uint2*)&Xl[xk*STRX + xn + 64] = *(const uint2*)(Xpl + 64);
        } else {
            float4 x0 = *(const float4*)Xp;
            float4 x1 = *(const float4*)(Xp + 64);
            if (XF) { x0 = xform4(x0, xk, xfStats, xfW, xfB); x1 = xform4(x1, xk, xfStats, xfW, xfB); }
            *(uint2*)&Xh[xk*STRX + xn]      = make_uint2(pk2(x0.x,x0.y), pk2(x0.z,x0.w));
            *(uint2*)&Xh[xk*STRX + xn + 64] = make_uint2(pk2(x1.x,x1.y), pk2(x1.z,x1.w));
            *(uint2*)&Xl[xk*STRX + xn]      = make_uint2(pk2(bflo(x0.x),bflo(x0.y)), pk2(bflo(x0.z),bflo(x0.w)));
            *(uint2*)&Xl[xk*STRX + xn + 64] = make_uint2(pk2(bflo(x1.x),bflo(x1.y)), pk2(bflo(x1.z),bflo(x1.w)));
        }
    }
    __syncthreads();

    for (int t = 0; t < nt_chunks; t++) {
        int cur = t & 1;
        uint4 rah, ral;
        uint2 xh0, xh1, xl0, xl1;
        float4 x0, x1;
        if (t + 1 < nt_chunks) {
            rah = *(const uint4*)(Aph + (t+1)*16);
            ral = *(const uint4*)(Apl + (t+1)*16);
            if (XBF) {
                xh0 = *(const uint2*)(Xph + (long)(t+1)*16*N);
                xh1 = *(const uint2*)(Xph + (long)(t+1)*16*N + 64);
                xl0 = *(const uint2*)(Xpl + (long)(t+1)*16*N);
                xl1 = *(const uint2*)(Xpl + (long)(t+1)*16*N + 64);
            } else {
                x0 = *(const float4*)(Xp + (long)(t+1)*16*N);
                x1 = *(const float4*)(Xp + (long)(t+1)*16*N + 64);
                if (XF) {
                    int k = (t+1)*16 + xk;
                    x0 = xform4(x0, k, xfStats, xfW, xfB);
                    x1 = xform4(x1, k, xfStats, xfW, xfB);
                }
            }
        }

        const u16* Ah = sm_ + cur*BUFSZ;
        const u16* Al = Ah + ABUF;
        const u16* Xh = Ah + 2*ABUF;
        const u16* Xl = Xh + XBUF;

        unsigned bh[4][2], bl[4][2];
        #pragma unroll
        for (int nt = 0; nt < 4; nt++) {
            int col = warp_n*32 + nt*8;
            unsigned ad = (unsigned)__cvta_generic_to_shared(&Xh[b_krow*STRX + col]);
            LDMX2T(bh[nt][0], bh[nt][1], ad);
            ad = (unsigned)__cvta_generic_to_shared(&Xl[b_krow*STRX + col]);
            LDMX2T(bl[nt][0], bl[nt][1], ad);
        }

        #pragma unroll
        for (int mt = 0; mt < 4; mt++) {
            int row = warp_m*64 + mt*16 + a_mrow;
            unsigned ah0,ah1,ah2,ah3, al0,al1,al2,al3;
            unsigned ad = (unsigned)__cvta_generic_to_shared(&Ah[row*STRA + a_koff]);
            LDMX4(ah0,ah1,ah2,ah3, ad);
            ad = (unsigned)__cvta_generic_to_shared(&Al[row*STRA + a_koff]);
            LDMX4(al0,al1,al2,al3, ad);
            #pragma unroll
            for (int nt = 0; nt < 4; nt++) {
                float* c = acc[mt][nt];
                MMA16816(c[0],c[1],c[2],c[3], ah0,ah1,ah2,ah3, bh[nt][0],bh[nt][1]);
                MMA16816(c[0],c[1],c[2],c[3], ah0,ah1,ah2,ah3, bl[nt][0],bl[nt][1]);
                MMA16816(c[0],c[1],c[2],c[3], al0,al1,al2,al3, bh[nt][0],bh[nt][1]);
            }
        }

        if (t + 1 < nt_chunks) {
            int nxt = cur ^ 1;
            u16* Ah2 = sm_ + nxt*BUFSZ;
            u16* Al2 = Ah2 + ABUF;
            u16* Xh2 = Ah2 + 2*ABUF;
            u16* Xl2 = Xh2 + XBUF;
            *(uint4*)&Ah2[arow*STRA + aq*8] = rah;
            *(uint4*)&Al2[arow*STRA + aq*8] = ral;
            if (XBF) {
                *(uint2*)&Xh2[xk*STRX + xn]      = xh0;
                *(uint2*)&Xh2[xk*STRX + xn + 64] = xh1;
                *(uint2*)&Xl2[xk*STRX + xn]      = xl0;
                *(uint2*)&Xl2[xk*STRX + xn + 64] = xl1;
            } else {
                *(uint2*)&Xh2[xk*STRX + xn]      = make_uint2(pk2(x0.x,x0.y), pk2(x0.z,x0.w));
                *(uint2*)&Xh2[xk*STRX + xn + 64] = make_uint2(pk2(x1.x,x1.y), pk2(x1.z,x1.w));
                *(uint2*)&Xl2[xk*STRX + xn]      = make_uint2(pk2(bflo(x0.x),bflo(x0.y)), pk2(bflo(x0.z),bflo(x0.w)));
                *(uint2*)&Xl2[xk*STRX + xn + 64] = make_uint2(pk2(bflo(x1.x),bflo(x1.y)), pk2(bflo(x1.z),bflo(x1.w)));
            }
            __syncthreads();
        }
    }

    int g = lane >> 2, tq = lane & 3;
    float s1 = 0.f, s2 = 0.f;
    #pragma unroll
    for (int mt = 0; mt < 4; mt++) {
        int r0 = m0 + warp_m*64 + mt*16 + g;
        float b0v = bias ? bias[r0]   : 0.f;
        float b1v = bias ? bias[r0+8] : 0.f;
        #pragma unroll
        for (int nt = 0; nt < 4; nt++) {
            int c = n0 + warp_n*32 + nt*8 + tq*2;
            float* a = acc[mt][nt];
            float v0 = a[0]+b0v, v1 = a[1]+b0v, v2 = a[2]+b1v, v3 = a[3]+b1v;
            *(float2*)&Yb[(long)r0*N + c]     = make_float2(v0, v1);
            *(float2*)&Yb[(long)(r0+8)*N + c] = make_float2(v2, v3);
            if (STATS) {
                s1 += v0 + v1 + v2 + v3;
                s2 += v0*v0 + v1*v1 + v2*v2 + v3*v3;
            }
        }
    }
    if (STATS) {
        __syncthreads();
        float* red = (float*)sm_;
        red[tid] = s1; red[tid + 256] = s2;
        __syncthreads();
        for (int o = 128; o > 0; o >>= 1) {
            if (tid < o) { red[tid] += red[tid+o]; red[tid+256] += red[tid+256+o]; }
            __syncthreads();
        }
        if (tid == 0) {
            partial[pIdx*2 + 0] = red[0];
            partial[pIdx*2 + 1] = red[256];
        }
    }
}

__global__ void __launch_bounds__(256, 2)
gemm_agg(const u16* __restrict__ Agh, const u16* __restrict__ Agl,
         const float* __restrict__ X, float* __restrict__ Y,
         int M, int N, int K,
         const float* __restrict__ xfStats, const float* __restrict__ xfW,
         const float* __restrict__ xfB, float* __restrict__ partial) {
    __shared__ __align__(16) u16 sm_[2*BUFSZ];
    int b = blockIdx.z;
    int pIdx = (b*gridDim.y + blockIdx.y)*gridDim.x + blockIdx.x;
    gemm_body<false,true,true>(Agh, Agl, nullptr, X + (long)b*K*N, nullptr, nullptr,
                               Y + (long)b*M*N, blockIdx.y*128, blockIdx.x*128, N, K, sm_,
                               xfStats + b*8, xfW, xfB, partial, pIdx);
}

__global__ void __launch_bounds__(256, 2)
gemm_qres(const u16* __restrict__ Wqh, const u16* __restrict__ Wql,
          const float* __restrict__ bq,
          const u16* __restrict__ Wsh, const u16* __restrict__ Wsl,
          const u16* __restrict__ Xh, const u16* __restrict__ Xl,
          float* __restrict__ Yq, float* __restrict__ Yres,
          float* __restrict__ partial, int N, int K) {
    __shared__ __align__(16) u16 sm_[2*BUFSZ];
    int b = blockIdx.z;
    const u16* xh = Xh + (long)b*K*N;
    const u16* xl = Xl + (long)b*K*N;
    if (blockIdx.y < 2) {
        gemm_body<true,false,false>(Wqh, Wql, bq, nullptr, xh, xl,
                                    Yq + (long)b*HID*N, blockIdx.y*128, blockIdx.x*128, N, K, sm_,
                                    nullptr, nullptr, nullptr, nullptr, 0);
    } else {
        int pIdx = (b*4 + (blockIdx.y - 2))*gridDim.x + blockIdx.x;
        gemm_body<true,false,true>(Wsh, Wsl, nullptr, nullptr, xh, xl,
                                   Yres + (long)b*COUT*N, (blockIdx.y - 2)*128, blockIdx.x*128, N, K, sm_,
                                   nullptr, nullptr, nullptr, partial, pIdx);
    }
}

__global__ void __launch_bounds__(256, 2)
gemm_kv(const u16* __restrict__ Wh, const u16* __restrict__ Wl,
        const float* __restrict__ bias,
        const u16* __restrict__ Xh, const u16* __restrict__ Xl,
        float* __restrict__ Y, int K, const int* __restrict__ cnt) {
    __shared__ __align__(16) u16 sm_[2*BUFSZ];
    int b = blockIdx.z;
    int nact = cnt[b];
    int npad4 = (nact + 3) & ~3;
    int N = TQ*npad4;
    int n0 = blockIdx.x*128;
    if (n0 >= N) return;
    gemm_body<true,false,false>(Wh, Wl, bias, nullptr,
                                Xh + (long)b*CIN*TQ*260, Xl + (long)b*CIN*TQ*260,
                                Y + (long)b*2*HID*TQ*260,
                                blockIdx.y*128, n0, N, K, sm_,
                                nullptr, nullptr, nullptr, nullptr, 0);
}

// ---------------- GroupNorm kernels ----------------
__global__ void gn_finalize(const float* __restrict__ partial, float* __restrict__ stats,
                            int nb, float invN) {
    int bg = threadIdx.x;
    if (bg >= 16) return;
    float s1 = 0.f, s2 = 0.f;
    for (int i = 0; i < nb; i++) {
        s1 += partial[(bg*nb + i)*2 + 0];
        s2 += partial[(bg*nb + i)*2 + 1];
    }
    float mean = s1*invN;
    float var  = fmaxf(s2*invN - mean*mean, 0.f);
    stats[bg*2 + 0] = mean;
    stats[bg*2 + 1] = 1.0f/sqrtf(var + 1e-5f);
}

__global__ void gn_apply(const float* __restrict__ x, float* __restrict__ out,
                         const float* __restrict__ w, const float* __restrict__ bvec,
                         const float* __restrict__ stats,
                         long groupSize, int T, int C, long n4) {
    long i4 = (long)blockIdx.x*blockDim.x + threadIdx.x;
    if (i4 >= n4) return;
    long e = i4*4;
    int bg = (int)(e / groupSize);
    int c  = (int)((e / T) % C);
    float mu = stats[bg*2], iv = stats[bg*2 + 1];
    float ww = w[c]*iv;
    float of = fmaf(-mu, ww, bvec[c]);
    float4 v = ((const float4*)x)[i4];
    v.x = fmaf(v.x, ww, of);
    v.y = fmaf(v.y, ww, of);
    v.z = fmaf(v.z, ww, of);
    v.w = fmaf(v.w, ww, of);
    ((float4*)out)[i4] = v;
}

__global__ void gn_fuse2(const float* __restrict__ agg, float* __restrict__ res_t,
                         const float* __restrict__ w2, const float* __restrict__ b2,
                         const float* __restrict__ wsc, const float* __restrict__ bsc,
                         const float* __restrict__ stats2, const float* __restrict__ statssc,
                         float* __restrict__ partial,
                         long groupSize, int T, int C) {
    long bg = blockIdx.y;
    long base4 = bg*(groupSize >> 2);
    float mu2 = stats2[bg*2],  inv2 = stats2[bg*2 + 1];
    float mus = statssc[bg*2], invs = statssc[bg*2 + 1];
    int tid = threadIdx.x;
    long gs4 = groupSize >> 2;
    float s1 = 0.f, s2 = 0.f;
    for (long i = (long)blockIdx.x*blockDim.x + tid; i < gs4; i += (long)gridDim.x*blockDim.x) {
        long i4 = base4 + i;
        long e = i4*4;
        int c = (int)((e / T) % C);
        float wa = w2[c]*inv2,  oa = fmaf(-mu2, wa, b2[c]);
        float wr = wsc[c]*invs, orr = fmaf(-mus, wr, bsc[c]);
        float4 a = ((const float4*)agg)[i4];
        float4 r = ((const float4*)res_t)[i4];
        float4 v;
        v.x = fmaxf(fmaf(a.x, wa, oa), 0.f) + fmaxf(fmaf(r.x, wr, orr), 0.f);
        v.y = fmaxf(fmaf(a.y, wa, oa), 0.f) + fmaxf(fmaf(r.y, wr, orr), 0.f);
        v.z = fmaxf(fmaf(a.z, wa, oa), 0.f) + fmaxf(fmaf(r.z, wr, orr), 0.f);
        v.w = fmaxf(fmaf(a.w, wa, oa), 0.f) + fmaxf(fmaf(r.w, wr, orr), 0.f);
        ((float4*)res_t)[i4] = v;
        s1 += v.x + v.y + v.z + v.w;
        s2 += v.x*v.x + v.y*v.y + v.z*v.z + v.w*v.w;
    }
    __shared__ float sh1[256], sh2[256];
    sh1[tid] = s1; sh2[tid] = s2;
    __syncthreads();
    for (int o = 128; o > 0; o >>= 1) {
        if (tid < o) { sh1[tid] += sh1[tid+o]; sh2[tid] += sh2[tid+o]; }
        __syncthreads();
    }
    if (tid == 0) {
        partial[(bg*gridDim.x + blockIdx.x)*2 + 0] = sh1[0];
        partial[(bg*gridDim.x + blockIdx.x)*2 + 1] = sh2[0];
    }
}

// ---------------- fused attention (SIMT, compacted K/V); gn1 partials ----------------
#define SM_Q   (32*68)
#define SM_K   (32*260)
#define SM_S   (68*260)
#define SMEM_FLOATS (SM_Q + SM_K + SM_S)
#define SMEM_BYTES  (SMEM_FLOATS*4)

__global__ void attn_kernel(const float* __restrict__ gq, const float* __restrict__ gkv,
                            const int* __restrict__ cnt, float* __restrict__ gout,
                            float* __restrict__ partial1) {
    extern __shared__ float sm[];
    float* Qs  = sm;
    float* KVs = Qs + SM_Q;
    float* S   = KVs + SM_K;
    __shared__ float Sinv[68];
    __shared__ float red1[256], red2[256];

    int q = blockIdx.x, g = blockIdx.y, b = blockIdx.z;
    int tid = threadIdx.x;
    int wid = tid >> 5, lane = tid & 31;
    long qbase = ((long)(b*HID + g*EDIM)*TQ + q)*TD;

    int nact  = cnt[b];
    int npad  = (nact + 3) & ~3;
    int ntile = npad >> 2;
    long kvs  = (long)TQ*npad;
    const float* kptr = gkv + (long)b*2*HID*TQ*260 + (long)(g*EDIM)*kvs + (long)q*npad;
    const float* vptr = kptr + (long)HID*kvs;

    for (int i = tid; i < SM_Q; i += 256) {
        int e = i/68, d = i%68;
        Qs[i] = (d < TD) ? gq[qbase + (long)e*TQ*TD + d] : 0.f;
    }
    // K load, guard-free float4 (KV GEMM wrote all npad4 columns; softmax zeroes S pads)
    for (int e = wid; e < 32; e += 8) {
        const float* kp = kptr + (long)e*kvs;
        for (int j4 = lane; j4 < ntile; j4 += 32)
            *(float4*)&KVs[e*260 + j4*4] = *(const float4*)(kp + j4*4);
    }
    __syncthreads();

    // S[d][j] = sum_e Q[e][d]*K[e][j]
    int ntt = 17*ntile;
    for (int t = tid; t < ntt; t += 256) {
        int dt = t/ntile, st = t%ntile;
        float acc[4][4];
        #pragma unroll
        for (int i = 0; i < 4; i++)
            #pragma unroll
            for (int j = 0; j < 4; j++) acc[i][j] = 0.f;
        #pragma unroll
        for (int e = 0; e < 32; e++) {
            float4 a  = *(const float4*)&Qs[e*68 + dt*4];
            float4 k4 = *(const float4*)&KVs[e*260 + st*4];
            acc[0][0] += a.x*k4.x; acc[0][1] += a.x*k4.y; acc[0][2] += a.x*k4.z; acc[0][3] += a.x*k4.w;
            acc[1][0] += a.y*k4.x; acc[1][1] += a.y*k4.y; acc[1][2] += a.y*k4.z; acc[1][3] += a.y*k4.w;
            acc[2][0] += a.z*k4.x; acc[2][1] += a.z*k4.y; acc[2][2] += a.z*k4.z; acc[2][3] += a.z*k4.w;
            acc[3][0] += a.w*k4.x; acc[3][1] += a.w*k4.y; acc[3][2] += a.w*k4.z; acc[3][3] += a.w*k4.w;
        }
        #pragma unroll
        for (int i = 0; i < 4; i++)
            #pragma unroll
            for (int j = 0; j < 4; j++)
                S[(dt*4 + i)*260 + st*4 + j] = acc[i][j];
    }
    __syncthreads();

    // Load V (guard-free float4, reusing K buffer) while softmax (single pass)
    for (int e = wid; e < 32; e += 8) {
        const float* vp = vptr + (long)e*kvs;
        for (int j4 = lane; j4 < ntile; j4 += 32)
            *(float4*)&KVs[e*260 + j4*4] = *(const float4*)(vp + j4*4);
    }

    for (int d = wid; d < TD; d += 8) {
        float sum = 0.f;
        for (int j = lane; j < nact; j += 32) {
            float e = fexp(S[d*260 + j]);
            S[d*260 + j] = e;
            sum += e;
        }
        #pragma unroll
        for (int o = 16; o > 0; o >>= 1) sum += __shfl_xor_sync(0xffffffffu, sum, o);
        if (lane == 0) Sinv[d] = 1.0f/sum;
        if (lane < npad - nact) S[d*260 + nact + lane] = 0.f;
    }
    __syncthreads();

    // O-phase main: 128 tasks (8 et x 16 dt, d<64) x 2 halves = 256 items, ONE round.
    long obase = qbase;
    int halfTiles = (ntile + 1) >> 1;
    float s1 = 0.f, s2 = 0.f;
    {
        int task = tid >> 1, half = tid & 1;
        int et = task >> 4, dt = task & 15;
        float acc[4][4];
        #pragma unroll
        for (int j = 0; j < 4; j++)
            #pragma unroll
            for (int i = 0; i < 4; i++) acc[j][i] = 0.f;
        int sA = half*halfTiles;
        int sB = min(ntile, sA + halfTiles);
        for (int s4 = sA; s4 < sB; s4++) {
            float4 a0 = *(const float4*)&S[(dt*4 + 0)*260 + s4*4];
            float4 a1 = *(const float4*)&S[(dt*4 + 1)*260 + s4*4];
            float4 a2 = *(const float4*)&S[(dt*4 + 2)*260 + s4*4];
            float4 a3 = *(const float4*)&S[(dt*4 + 3)*260 + s4*4];
            float4 v0 = *(const float4*)&KVs[(et*4 + 0)*260 + s4*4];
            float4 v1 = *(const float4*)&KVs[(et*4 + 1)*260 + s4*4];
            float4 v2 = *(const float4*)&KVs[(et*4 + 2)*260 + s4*4];
            float4 v3 = *(const float4*)&KVs[(et*4 + 3)*260 + s4*4];
            acc[0][0] += a0.x*v0.x + a0.y*v0.y + a0.z*v0.z + a0.w*v0.w;
            acc[0][1] += a1.x*v0.x + a1.y*v0.y + a1.z*v0.z + a1.w*v0.w;
            acc[0][2] += a2.x*v0.x + a2.y*v0.y + a2.z*v0.z + a2.w*v0.w;
            acc[0][3] += a3.x*v0.x + a3.y*v0.y + a3.z*v0.z + a3.w*v0.w;
            acc[1][0] += a0.x*v1.x + a0.y*v1.y + a0.z*v1.z + a0.w*v1.w;
            acc[1][1] += a1.x*v1.x + a1.y*v1.y + a1.z*v1.z + a1.w*v1.w;
            acc[1][2] += a2.x*v1.x + a2.y*v1.y + a2.z*v1.z + a2.w*v1.w;
            acc[1][3] += a3.x*v1.x + a3.y*v1.y + a3.z*v1.z + a3.w*v1.w;
            acc[2][0] += a0.x*v2.x + a0.y*v2.y + a0.z*v2.z + a0.w*v2.w;
            acc[2][1] += a1.x*v2.x + a1.y*v2.y + a1.z*v2.z + a1.w*v2.w;
            acc[2][2] += a2.x*v2.x + a2.y*v2.y + a2.z*v2.z + a2.w*v2.w;
            acc[2][3] += a3.x*v2.x + a3.y*v2.y + a3.z*v2.z + a3.w*v2.w;
            acc[3][0] += a0.x*v3.x + a0.y*v3.y + a0.z*v3.z + a0.w*v3.w;
            acc[3][1] += a1.x*v3.x + a1.y*v3.y + a1.z*v3.z + a1.w*v3.w;
            acc[3][2] += a2.x*v3.x + a2.y*v3.y + a2.z*v3.z + a2.w*v3.w;
            acc[3][3] += a3.x*v3.x + a3.y*v3.y + a3.z*v3.z + a3.w*v3.w;
        }
        #pragma unroll
        for (int j = 0; j < 4; j++)
            #pragma unroll
            for (int i = 0; i < 4; i++)
                acc[j][i] += __shfl_xor_sync(0xffffffffu, acc[j][i], 1);
        if (half == 0) {
            #pragma unroll
            for (int j = 0; j < 4; j++)
                #pragma unroll
                for (int i = 0; i < 4; i++) {
                    int d = dt*4 + i;
                    float v = acc[j][i]*Sinv[d];
                    gout[obase + (long)(et*4 + j)*TQ*TD + d] = v;
                    s1 += v; s2 += v*v;
                }
        }
    }
    // O-phase tail: d=64 column
    {
        int e = tid >> 3, oct = tid & 7;
        int octTiles = (ntile + 7) >> 3;
        int sA = oct*octTiles;
        int sB = min(ntile, sA + octTiles);
        float a = 0.f;
        for (int s4 = sA; s4 < sB; s4++) {
            float4 sv = *(const float4*)&S[64*260 + s4*4];
            float4 vv = *(const float4*)&KVs[e*260 + s4*4];
            a += sv.x*vv.x + sv.y*vv.y + sv.z*vv.z + sv.w*vv.w;
        }
        a += __shfl_xor_sync(0xffffffffu, a, 1);
        a += __shfl_xor_sync(0xffffffffu, a, 2);
        a += __shfl_xor_sync(0xffffffffu, a, 4);
        if (oct == 0) {
            float v = a*Sinv[64];
            gout[obase + (long)e*TQ*TD + 64] = v;
            s1 += v; s2 += v*v;
        }
    }

    red1[tid] = s1; red2[tid] = s2;
    __syncthreads();
    for (int o = 128; o > 0; o >>= 1) {
        if (tid < o) { red1[tid] += red1[tid+o]; red2[tid] += red2[tid+o]; }
        __syncthreads();
    }
    if (tid == 0) {
        int pIdx = (b*4 + (g >> 1))*512 + (g & 1)*256 + q;
        partial1[pIdx*2 + 0] = red1[0];
        partial1[pIdx*2 + 1] = red2[0];
    }
}

// ---------------- host orchestration ----------------
extern "C" void kernel_launch(void* const* d_in, const int* in_sizes, int n_in,
                              void* d_out, int out_size) {
    const float* corr   = (const float*)d_in[0];
    const int*   smask  = (const int*)  d_in[1];
    const float* W_sc   = (const float*)d_in[2];
    const float* gnscw  = (const float*)d_in[3];
    const float* gnscb  = (const float*)d_in[4];
    const float* W_qkv  = (const float*)d_in[5];
    const float* b_qkv  = (const float*)d_in[6];
    const float* gn1w   = (const float*)d_in[7];
    const float* gn1b   = (const float*)d_in[8];
    const float* W_agg  = (const float*)d_in[9];
    const float* gn2w   = (const float*)d_in[10];
    const float* gn2b   = (const float*)d_in[11];
    const float* gnow   = (const float*)d_in[12];
    const float* gnob   = (const float*)d_in[13];
    float* out = (float*)d_out;

    u16 *poolh, *pooll, *corrh, *corrl, *wqkvh, *wqkvl, *wsch, *wscl, *waggh, *waggl;
    float *kv, *q, *res, *att, *agg;
    float *partial, *partial1, *stats, *stats_sc, *stats1, *stats2;
    int *sidx, *cnt;
    cudaGetSymbolAddress((void**)&poolh,   g_pooledh);
    cudaGetSymbolAddress((void**)&pooll,   g_pooledl);
    cudaGetSymbolAddress((void**)&corrh,   g_corrch);
    cudaGetSymbolAddress((void**)&corrl,   g_corrcl);
    cudaGetSymbolAddress((void**)&wqkvh,   g_wqkvh);
    cudaGetSymbolAddress((void**)&wqkvl,   g_wqkvl);
    cudaGetSymbolAddress((void**)&wsch,    g_wsch);
    cudaGetSymbolAddress((void**)&wscl,    g_wscl);
    cudaGetSymbolAddress((void**)&waggh,   g_waggh);
    cudaGetSymbolAddress((void**)&waggl,   g_waggl);
    cudaGetSymbolAddress((void**)&kv,      g_kv);
    cudaGetSymbolAddress((void**)&q,       g_q);
    cudaGetSymbolAddress((void**)&res,     g_res);
    cudaGetSymbolAddress((void**)&att,     g_att);
    cudaGetSymbolAddress((void**)&agg,     g_agg);
    cudaGetSymbolAddress((void**)&sidx,    g_sidx);
    cudaGetSymbolAddress((void**)&cnt,     g_cnt);
    cudaGetSymbolAddress((void**)&partial, g_partial);
    cudaGetSymbolAddress((void**)&partial1,g_partial1);
    cudaGetSymbolAddress((void**)&stats,   g_stats);
    cudaGetSymbolAddress((void**)&stats_sc,g_stats_sc);
    cudaGetSymbolAddress((void**)&stats1,  g_stats1);
    cudaGetSymbolAddress((void**)&stats2,  g_stats2);

    const int NPOOL = TQ*TD;     // 16640
    const int NKVMAX = TQ*260;   // 66560

    const long gsC = (long)(COUT/4)*NPOOL;
    const long gsH = (long)(HID/4)*NPOOL;
    const float invC = 1.0f/(float)gsC;
    const float invH = 1.0f/(float)gsH;

    // 0. weight pre-split (tiny)
    wsplit<<<(768*CIN + 255)/256, 256>>>(W_qkv, wqkvh, wqkvl, 768*CIN);
    wsplit<<<(COUT*CIN + 255)/256, 256>>>(W_sc,  wsch,  wscl,  COUT*CIN);
    wsplit<<<(COUT*HID + 255)/256, 256>>>(W_agg, waggh, waggl, COUT*HID);

    // 1. mask compaction, pool + compact (bf16 hi/lo planes)
    mask_compact<<<BB, 256>>>(smask, sidx, cnt);
    pool_compact<<<BB*CIN*TQ/8, 256>>>(corr, poolh, pooll, corrh, corrl, sidx, cnt);

    // 2. GEMMs
    gemm_qres<<<dim3(NPOOL/128, 6, BB), 256>>>(wqkvh, wqkvl, b_qkv, wsch, wscl,
                                               poolh, pooll, q, res, partial, NPOOL, CIN);
    gemm_kv<<<dim3(NKVMAX/128, 2*HID/128, BB), 256>>>(wqkvh + HID*CIN, wqkvl + HID*CIN,
                                                      b_qkv + HID, corrh, corrl, kv, CIN, cnt);
    gn_finalize<<<1, 16>>>(partial, stats_sc, 130, invC);

    // 3. attention (occ-2 friendly smem: 113 KB dyn)
    cudaFuncSetAttribute(attn_kernel, cudaFuncAttributeMaxDynamicSharedMemorySize, SMEM_BYTES);
    attn_kernel<<<dim3(TQ, NHEAD, BB), 256, SMEM_BYTES>>>(q, kv, cnt, att, partial1);
    gn_finalize<<<1, 16>>>(partial1, stats1, 512, invH);

    // 4. agg = W_agg @ relu(gn1(att)), gn1 fused in loader; emits gn2 partials
    gemm_agg<<<dim3(NPOOL/128, COUT/128, BB), 256>>>(waggh, waggl, att, agg, COUT, NPOOL, HID,
                                                     stats1, gn1w, gn1b, partial);
    gn_finalize<<<1, 16>>>(partial, stats2, 130, invC);

    // 5. fuse + gn_out
    gn_fuse2<<<dim3(128, 16), 256>>>(agg, res, gn2w, gn2b, gnscw, gnscb,
                                     stats2, stats_sc, partial, gsC, NPOOL, COUT);
    gn_finalize<<<1, 16>>>(partial, stats, 128, invC);
    {
        long n4 = ((long)BB*COUT*NPOOL) >> 2;
        gn_apply<<<(unsigned)((n4 + 255)/256), 256>>>(res, out, gnow, gnob, stats, gsC, NPOOL, COUT, n4);
    }
}